// round 1
// baseline (speedup 1.0000x reference)
#include <cuda_runtime.h>
#include <math.h>

#define NN 150000
#define UU 100000
#define II 50000
#define DD 64
#define EE 2000000
#define LL 3

// -------- device scratch (no allocations allowed) --------
__device__ float g_cur[NN * DD];
__device__ float g_gnn[NN * DD];
__device__ float g_fine[NN * DD];
__device__ float g_gvals[EE];
__device__ float g_scores[EE];
__device__ float g_dis[NN];
__device__ float g_invn[NN];
__device__ float g_rowsum[NN];
__device__ int   g_deg[NN];

// -------- kernels --------

__global__ void count_deg_kernel(const int* __restrict__ rows) {
    int e = blockIdx.x * blockDim.x + threadIdx.x;
    if (e < EE) atomicAdd(&g_deg[rows[e]], 1);
}

__global__ void dis_kernel() {
    int n = blockIdx.x * blockDim.x + threadIdx.x;
    if (n < NN) {
        float dg = (float)g_deg[n];
        g_dis[n] = dg > 0.f ? rsqrtf(dg) : 0.f;
    }
}

__global__ void gvals_kernel(const int* __restrict__ rows, const int* __restrict__ cols) {
    int e = blockIdx.x * blockDim.x + threadIdx.x;
    if (e < EE) g_gvals[e] = g_dis[rows[e]] * g_dis[cols[e]];
}

// cur = emb0; out[0:N*D] = emb0 (acc)
__global__ void init_kernel(const float* __restrict__ user_emb,
                            const float* __restrict__ item_emb,
                            float* __restrict__ out) {
    int i = blockIdx.x * blockDim.x + threadIdx.x;
    if (i < NN * DD) {
        float v = (i < UU * DD) ? user_emb[i] : item_emb[i - UU * DD];
        g_cur[i] = v;
        out[i] = v;
    }
}

// warp-per-edge scatter SpMM: gnn[rows[e]] += gvals[e] * cur[cols[e]]
__global__ void spmm_gnn_kernel(const int* __restrict__ rows, const int* __restrict__ cols) {
    int gtid = blockIdx.x * blockDim.x + threadIdx.x;
    int e = gtid >> 5;
    int lane = gtid & 31;
    if (e >= EE) return;
    int r = rows[e];
    int c = cols[e];
    float w = g_gvals[e];
    const float2* xv = (const float2*)(g_cur + (size_t)c * DD);
    float2 v = xv[lane];
    float* yr = g_gnn + (size_t)r * DD + lane * 2;
    atomicAdd(yr,     w * v.x);
    atomicAdd(yr + 1, w * v.y);
}

// warp-per-node: invn[n] = 1 / max(||gnn[n]||, eps)
__global__ void invn_kernel() {
    int gtid = blockIdx.x * blockDim.x + threadIdx.x;
    int n = gtid >> 5;
    int lane = gtid & 31;
    if (n >= NN) return;
    const float2* xv = (const float2*)(g_gnn + (size_t)n * DD);
    float2 v = xv[lane];
    float s = v.x * v.x + v.y * v.y;
    #pragma unroll
    for (int off = 16; off > 0; off >>= 1)
        s += __shfl_xor_sync(0xFFFFFFFFu, s, off);
    if (lane == 0) {
        float nrm = sqrtf(s);
        g_invn[n] = 1.0f / fmaxf(nrm, 1e-12f);
    }
}

// warp-per-edge: scores[e] = (cos(gnn[r],gnn[c]) + 1)/2; rowsum[r] += s
__global__ void score_kernel(const int* __restrict__ rows, const int* __restrict__ cols) {
    int gtid = blockIdx.x * blockDim.x + threadIdx.x;
    int e = gtid >> 5;
    int lane = gtid & 31;
    if (e >= EE) return;
    int r = rows[e];
    int c = cols[e];
    const float2* av = (const float2*)(g_gnn + (size_t)r * DD);
    const float2* bv = (const float2*)(g_gnn + (size_t)c * DD);
    float2 a = av[lane];
    float2 b = bv[lane];
    float d = a.x * b.x + a.y * b.y;
    #pragma unroll
    for (int off = 16; off > 0; off >>= 1)
        d += __shfl_xor_sync(0xFFFFFFFFu, d, off);
    if (lane == 0) {
        float s = (d * g_invn[r] * g_invn[c] + 1.0f) * 0.5f;
        g_scores[e] = s;
        atomicAdd(&g_rowsum[r], s);
    }
}

__global__ void dinv_kernel() {
    int n = blockIdx.x * blockDim.x + threadIdx.x;
    if (n < NN) {
        float rs = g_rowsum[n];
        g_rowsum[n] = rs > 0.f ? 1.0f / rs : 0.f;
    }
}

// warp-per-edge: fine[rows[e]] += (dinv[rows[e]] * scores[e]) * cur[cols[e]]
__global__ void spmm_fine_kernel(const int* __restrict__ rows, const int* __restrict__ cols) {
    int gtid = blockIdx.x * blockDim.x + threadIdx.x;
    int e = gtid >> 5;
    int lane = gtid & 31;
    if (e >= EE) return;
    int r = rows[e];
    int c = cols[e];
    float w = g_rowsum[r] * g_scores[e];
    const float2* xv = (const float2*)(g_cur + (size_t)c * DD);
    float2 v = xv[lane];
    float* yr = g_fine + (size_t)r * DD + lane * 2;
    atomicAdd(yr,     w * v.x);
    atomicAdd(yr + 1, w * v.y);
}

// cur = gnn + fine; acc(out) += cur; store fine slices to stacked outputs
__global__ void finalize_kernel(float* __restrict__ out, int layer) {
    int i = blockIdx.x * blockDim.x + threadIdx.x;
    if (i >= NN * DD) return;
    float f = g_fine[i];
    float cn = g_gnn[i] + f;
    g_cur[i] = cn;
    out[i] += cn;
    const int ND = NN * DD;
    const int UD = UU * DD;
    const int ID = II * DD;
    if (i < UD) {
        // user_fine[layer]
        out[ND + layer * UD + i] = f;
    } else {
        // item_fine[layer]
        out[ND + LL * UD + layer * ID + (i - UD)] = f;
    }
}

// -------- launch --------
extern "C" void kernel_launch(void* const* d_in, const int* in_sizes, int n_in,
                              void* d_out, int out_size) {
    const float* user_emb = (const float*)d_in[0];
    const float* item_emb = (const float*)d_in[1];
    const int*   rows     = (const int*)d_in[2];
    const int*   cols     = (const int*)d_in[3];
    float* out = (float*)d_out;

    void *p_gnn, *p_fine, *p_rowsum, *p_deg;
    cudaGetSymbolAddress(&p_gnn, g_gnn);
    cudaGetSymbolAddress(&p_fine, g_fine);
    cudaGetSymbolAddress(&p_rowsum, g_rowsum);
    cudaGetSymbolAddress(&p_deg, g_deg);

    cudaStream_t s = 0;
    const int TB = 256;
    const int grid_E     = (EE + TB - 1) / TB;          // thread-per-edge
    const int grid_Ewarp = (EE * 32 + TB - 1) / TB;     // warp-per-edge
    const int grid_N     = (NN + TB - 1) / TB;
    const int grid_Nwarp = (NN * 32 + TB - 1) / TB;
    const int grid_ND    = (NN * DD + TB - 1) / TB;

    cudaMemsetAsync(p_deg, 0, NN * sizeof(int), s);
    count_deg_kernel<<<grid_E, TB, 0, s>>>(rows);
    dis_kernel<<<grid_N, TB, 0, s>>>();
    gvals_kernel<<<grid_E, TB, 0, s>>>(rows, cols);
    init_kernel<<<grid_ND, TB, 0, s>>>(user_emb, item_emb, out);

    for (int l = 0; l < LL; l++) {
        cudaMemsetAsync(p_gnn, 0, (size_t)NN * DD * sizeof(float), s);
        spmm_gnn_kernel<<<grid_Ewarp, TB, 0, s>>>(rows, cols);
        invn_kernel<<<grid_Nwarp, TB, 0, s>>>();
        cudaMemsetAsync(p_rowsum, 0, NN * sizeof(float), s);
        score_kernel<<<grid_Ewarp, TB, 0, s>>>(rows, cols);
        dinv_kernel<<<grid_N, TB, 0, s>>>();
        cudaMemsetAsync(p_fine, 0, (size_t)NN * DD * sizeof(float), s);
        spmm_fine_kernel<<<grid_Ewarp, TB, 0, s>>>(rows, cols);
        finalize_kernel<<<grid_ND, TB, 0, s>>>(out, l);
    }
}

// round 3
// speedup vs baseline: 1.6057x; 1.6057x over previous
#include <cuda_runtime.h>
#include <math.h>

#define NN 150000
#define UU 100000
#define II 50000
#define DD 64
#define EE 2000000
#define LL 3
#define CAP 128   // per-warp score cache (max degree safeguard; recompute fallback)
#define WPB 8     // warps per block in row kernels

// -------- device scratch (no allocations allowed) --------
__device__ float g_curA[NN * DD];
__device__ float g_curB[NN * DD];
__device__ float g_gnn[NN * DD];
__device__ float g_invn[NN];
__device__ float g_dis[NN];
__device__ int   g_deg[NN];
__device__ int   g_rowptr[NN + 1];
__device__ int   g_cursor[NN];
__device__ int   g_ecol[EE];
__device__ float g_eval[EE];

// ---------------- setup kernels ----------------

__global__ void hist_kernel(const int* __restrict__ rows) {
    int e = blockIdx.x * blockDim.x + threadIdx.x;
    if (e < EE) atomicAdd(&g_deg[rows[e]], 1);
}

__global__ void dis_kernel() {
    int n = blockIdx.x * blockDim.x + threadIdx.x;
    if (n < NN) {
        float dg = (float)g_deg[n];
        g_dis[n] = dg > 0.f ? rsqrtf(dg) : 0.f;
    }
}

// single-block exclusive scan of g_deg -> g_rowptr (NN+1 entries)
__global__ void scan_kernel() {
    __shared__ int s[1024];
    int carry = 0;
    if (threadIdx.x == 0) g_rowptr[0] = 0;
    for (int base = 0; base < NN; base += 1024) {
        int i = base + threadIdx.x;
        int v = (i < NN) ? g_deg[i] : 0;
        s[threadIdx.x] = v;
        __syncthreads();
        // Hillis-Steele inclusive scan
        #pragma unroll
        for (int off = 1; off < 1024; off <<= 1) {
            int t = (threadIdx.x >= off) ? s[threadIdx.x - off] : 0;
            __syncthreads();
            s[threadIdx.x] += t;
            __syncthreads();
        }
        if (i < NN) g_rowptr[i + 1] = carry + s[threadIdx.x];
        carry += s[1023];
        __syncthreads();
    }
}

// scatter edges into CSR order; e_val = dis[r]*dis[c]
__global__ void scatter_kernel(const int* __restrict__ rows, const int* __restrict__ cols) {
    int e = blockIdx.x * blockDim.x + threadIdx.x;
    if (e >= EE) return;
    int r = rows[e];
    int c = cols[e];
    int pos = atomicAdd(&g_cursor[r], 1);
    g_ecol[pos] = c;
    g_eval[pos] = g_dis[r] * g_dis[c];
}

// cur = emb0; out[0:N*D] = emb0 (acc starts at emb0)
__global__ void init_kernel(const float* __restrict__ user_emb,
                            const float* __restrict__ item_emb,
                            float* __restrict__ out) {
    int i = blockIdx.x * blockDim.x + threadIdx.x;
    if (i < NN * DD) {
        float v = (i < UU * DD) ? user_emb[i] : item_emb[i - UU * DD];
        g_curA[i] = v;
        out[i] = v;
    }
}

// ---------------- per-layer kernels ----------------

// warp-per-row gather SpMM: gnn[r] = sum_e g_e * cur[col_e]; fused invn
__global__ void __launch_bounds__(WPB * 32)
layer1_kernel(const float* __restrict__ cur) {
    int w = (blockIdx.x * blockDim.x + threadIdx.x) >> 5;
    int lane = threadIdx.x & 31;
    if (w >= NN) return;
    int start = g_rowptr[w];
    int end   = g_rowptr[w + 1];
    float ax = 0.f, ay = 0.f;
    for (int j = start; j < end; j += 32) {
        int idx = j + lane;
        int c = 0; float g = 0.f;
        if (idx < end) { c = g_ecol[idx]; g = g_eval[idx]; }
        int cnt = min(32, end - j);
        for (int t = 0; t < cnt; t++) {
            int   cc = __shfl_sync(0xFFFFFFFFu, c, t);
            float gg = __shfl_sync(0xFFFFFFFFu, g, t);
            float2 v = __ldg(((const float2*)(cur + (size_t)cc * DD)) + lane);
            ax = fmaf(gg, v.x, ax);
            ay = fmaf(gg, v.y, ay);
        }
    }
    ((float2*)(g_gnn + (size_t)w * DD))[lane] = make_float2(ax, ay);
    float ss = ax * ax + ay * ay;
    #pragma unroll
    for (int o = 16; o > 0; o >>= 1) ss += __shfl_xor_sync(0xFFFFFFFFu, ss, o);
    if (lane == 0) g_invn[w] = 1.0f / fmaxf(sqrtf(ss), 1e-12f);
}

// warp-per-row fused: scores + rowsum + fine-SpMM + finalize
// reads gnn, invn, cur_old; writes cur_new, out (acc + fine slices)
__global__ void __launch_bounds__(WPB * 32)
layer2_kernel(const float* __restrict__ cur_old,
              float* __restrict__ cur_new,
              float* __restrict__ out, int layer) {
    __shared__ float s_sc[WPB][CAP];
    int w = (blockIdx.x * blockDim.x + threadIdx.x) >> 5;
    int lane = threadIdx.x & 31;
    int wl = threadIdx.x >> 5;
    if (w >= NN) return;
    int start = g_rowptr[w];
    int end   = g_rowptr[w + 1];
    float2 gr = ((const float2*)(g_gnn + (size_t)w * DD))[lane];
    float invr = g_invn[w];

    float rowsum = 0.f;
    for (int j = start; j < end; j++) {
        int c = g_ecol[j];
        float2 gc = __ldg(((const float2*)(g_gnn + (size_t)c * DD)) + lane);
        float d = gr.x * gc.x + gr.y * gc.y;
        #pragma unroll
        for (int o = 16; o > 0; o >>= 1) d += __shfl_xor_sync(0xFFFFFFFFu, d, o);
        float s = (d * invr * g_invn[c] + 1.0f) * 0.5f;
        rowsum += s;
        if (lane == 0 && (j - start) < CAP) s_sc[wl][j - start] = s;
    }
    __syncwarp();
    float dinv = rowsum > 0.f ? 1.0f / rowsum : 0.f;

    float fx = 0.f, fy = 0.f;
    for (int j = start; j < end; j++) {
        int c = g_ecol[j];
        float s;
        if ((j - start) < CAP) {
            s = s_sc[wl][j - start];
        } else {
            float2 gc = __ldg(((const float2*)(g_gnn + (size_t)c * DD)) + lane);
            float d = gr.x * gc.x + gr.y * gc.y;
            #pragma unroll
            for (int o = 16; o > 0; o >>= 1) d += __shfl_xor_sync(0xFFFFFFFFu, d, o);
            s = (d * invr * g_invn[c] + 1.0f) * 0.5f;
        }
        float wgt = dinv * s;
        float2 v = __ldg(((const float2*)(cur_old + (size_t)c * DD)) + lane);
        fx = fmaf(wgt, v.x, fx);
        fy = fmaf(wgt, v.y, fy);
    }

    // fine slice -> out (stacked layout: [acc(N,D)][user_fine(L,U,D)][item_fine(L,I,D)])
    size_t fpos;
    if (w < UU)
        fpos = (size_t)NN * DD + (size_t)layer * UU * DD + (size_t)w * DD;
    else
        fpos = (size_t)NN * DD + (size_t)LL * UU * DD + (size_t)layer * II * DD
             + (size_t)(w - UU) * DD;
    ((float2*)(out + fpos))[lane] = make_float2(fx, fy);

    float cx = gr.x + fx, cy = gr.y + fy;           // cur_next = gnn + fine
    ((float2*)(cur_new + (size_t)w * DD))[lane] = make_float2(cx, cy);

    float2* o = (float2*)(out + (size_t)w * DD);    // acc += cur_next
    float2 ov = o[lane];
    o[lane] = make_float2(ov.x + cx, ov.y + cy);
}

// ---------------- launch ----------------
extern "C" void kernel_launch(void* const* d_in, const int* in_sizes, int n_in,
                              void* d_out, int out_size) {
    const float* user_emb = (const float*)d_in[0];
    const float* item_emb = (const float*)d_in[1];
    const int*   rows     = (const int*)d_in[2];
    const int*   cols     = (const int*)d_in[3];
    float* out = (float*)d_out;

    void *p_deg, *p_rowptr, *p_cursor, *p_curA, *p_curB;
    cudaGetSymbolAddress(&p_deg, g_deg);
    cudaGetSymbolAddress(&p_rowptr, g_rowptr);
    cudaGetSymbolAddress(&p_cursor, g_cursor);
    cudaGetSymbolAddress(&p_curA, g_curA);
    cudaGetSymbolAddress(&p_curB, g_curB);

    cudaStream_t s = 0;
    const int TB = 256;
    const int grid_E    = (EE + TB - 1) / TB;
    const int grid_N    = (NN + TB - 1) / TB;
    const int grid_ND   = (NN * DD + TB - 1) / TB;
    const int grid_RowW = (NN * 32 + TB - 1) / TB;   // warp-per-row

    cudaMemsetAsync(p_deg, 0, NN * sizeof(int), s);
    hist_kernel<<<grid_E, TB, 0, s>>>(rows);
    dis_kernel<<<grid_N, TB, 0, s>>>();
    scan_kernel<<<1, 1024, 0, s>>>();
    cudaMemcpyAsync(p_cursor, p_rowptr, NN * sizeof(int), cudaMemcpyDeviceToDevice, s);
    scatter_kernel<<<grid_E, TB, 0, s>>>(rows, cols);
    init_kernel<<<grid_ND, TB, 0, s>>>(user_emb, item_emb, out);

    float* bufA = (float*)p_curA;
    float* bufB = (float*)p_curB;
    for (int l = 0; l < LL; l++) {
        layer1_kernel<<<grid_RowW, TB, 0, s>>>(bufA);
        layer2_kernel<<<grid_RowW, TB, 0, s>>>(bufA, bufB, out, l);
        float* t = bufA; bufA = bufB; bufB = t;
    }
}

// round 4
// speedup vs baseline: 3.1439x; 1.9579x over previous
#include <cuda_runtime.h>
#include <math.h>

#define NN 150000
#define UU 100000
#define II 50000
#define DD 64
#define EE 2000000
#define LL 3
#define WPB 8
#define SCAN_B 1024
#define NBLK ((NN + SCAN_B - 1) / SCAN_B)   // 147

// -------- device scratch (no allocations allowed) --------
__device__ float g_curA[NN * DD];
__device__ float g_curB[NN * DD];
__device__ float g_gnn[NN * DD];
__device__ float g_invn[NN];
__device__ float g_dis[NN];
__device__ int   g_deg[NN];
__device__ int   g_rowptr[NN + 1];
__device__ int   g_cursor[NN];
__device__ int   g_ecol[EE];
__device__ float g_eval[EE];
__device__ int   g_bsum[NBLK + 1];
__device__ int   g_boff[NBLK + 1];

// ---------------- setup kernels ----------------

__global__ void hist_kernel(const int* __restrict__ rows) {
    int e = blockIdx.x * blockDim.x + threadIdx.x;
    if (e < EE) atomicAdd(&g_deg[rows[e]], 1);
}

// per-block inclusive scan of deg; also computes dis
__global__ void scan1_kernel() {
    __shared__ int s[SCAN_B];
    int i = blockIdx.x * SCAN_B + threadIdx.x;
    int v = (i < NN) ? g_deg[i] : 0;
    if (i < NN) g_dis[i] = v > 0 ? rsqrtf((float)v) : 0.f;
    s[threadIdx.x] = v;
    __syncthreads();
    #pragma unroll
    for (int off = 1; off < SCAN_B; off <<= 1) {
        int t = (threadIdx.x >= off) ? s[threadIdx.x - off] : 0;
        __syncthreads();
        s[threadIdx.x] += t;
        __syncthreads();
    }
    if (i < NN) g_rowptr[i + 1] = s[threadIdx.x];   // within-block inclusive
    if (threadIdx.x == SCAN_B - 1) g_bsum[blockIdx.x] = s[SCAN_B - 1];
}

// single small block scans the 147 block sums -> exclusive offsets
__global__ void scan2_kernel() {
    __shared__ int s[256];
    int t = threadIdx.x;
    int v = (t < NBLK) ? g_bsum[t] : 0;
    s[t] = v;
    __syncthreads();
    #pragma unroll
    for (int off = 1; off < 256; off <<= 1) {
        int x = (t >= off) ? s[t - off] : 0;
        __syncthreads();
        s[t] += x;
        __syncthreads();
    }
    if (t < NBLK) g_boff[t] = s[t] - v;   // exclusive
}

// finalize rowptr; also produce cursor (exclusive start per row)
__global__ void scan3_kernel() {
    int i = blockIdx.x * blockDim.x + threadIdx.x;
    if (i == 0) g_rowptr[0] = 0;
    if (i < NN) {
        int fin = g_rowptr[i + 1] + g_boff[i / SCAN_B];
        g_rowptr[i + 1] = fin;
        g_cursor[i] = fin - g_deg[i];
    }
}

// scatter edges into CSR order; e_val = dis[r]*dis[c]
__global__ void scatter_kernel(const int* __restrict__ rows, const int* __restrict__ cols) {
    int e = blockIdx.x * blockDim.x + threadIdx.x;
    if (e >= EE) return;
    int r = rows[e];
    int c = cols[e];
    int pos = atomicAdd(&g_cursor[r], 1);
    g_ecol[pos] = c;
    g_eval[pos] = g_dis[r] * g_dis[c];
}

__global__ void init_kernel(const float* __restrict__ user_emb,
                            const float* __restrict__ item_emb,
                            float* __restrict__ out) {
    int i = blockIdx.x * blockDim.x + threadIdx.x;
    if (i < NN * DD) {
        float v = (i < UU * DD) ? user_emb[i] : item_emb[i - UU * DD];
        g_curA[i] = v;
        out[i] = v;
    }
}

// ---------------- per-layer kernels ----------------

// warp-per-row gather SpMM: gnn[r] = sum_e g_e * cur[col_e]; fused invn
__global__ void __launch_bounds__(WPB * 32)
layer1_kernel(const float* __restrict__ cur) {
    int w = (blockIdx.x * blockDim.x + threadIdx.x) >> 5;
    int lane = threadIdx.x & 31;
    if (w >= NN) return;
    int start = g_rowptr[w];
    int end   = g_rowptr[w + 1];
    float ax = 0.f, ay = 0.f;
    for (int j = start; j < end; j += 32) {
        int idx = j + lane;
        int c = 0; float g = 0.f;
        if (idx < end) { c = g_ecol[idx]; g = g_eval[idx]; }
        int cnt = min(32, end - j);
        for (int t = 0; t < cnt; t++) {
            int   cc = __shfl_sync(0xFFFFFFFFu, c, t);
            float gg = __shfl_sync(0xFFFFFFFFu, g, t);
            float2 v = __ldg(((const float2*)(cur + (size_t)cc * DD)) + lane);
            ax = fmaf(gg, v.x, ax);
            ay = fmaf(gg, v.y, ay);
        }
    }
    ((float2*)(g_gnn + (size_t)w * DD))[lane] = make_float2(ax, ay);
    float ss = ax * ax + ay * ay;
    #pragma unroll
    for (int o = 16; o > 0; o >>= 1) ss += __shfl_xor_sync(0xFFFFFFFFu, ss, o);
    if (lane == 0) g_invn[w] = 1.0f / fmaxf(sqrtf(ss), 1e-12f);
}

// warp-per-row FUSED single pass: score + rowsum + unnormalized fine + finalize
// fine[r] = dinv * sum_e s_e * cur[c_e]  (dinv applied once at the end)
__global__ void __launch_bounds__(WPB * 32)
layer2_kernel(const float* __restrict__ cur_old,
              float* __restrict__ cur_new,
              float* __restrict__ out, int layer) {
    int w = (blockIdx.x * blockDim.x + threadIdx.x) >> 5;
    int lane = threadIdx.x & 31;
    if (w >= NN) return;
    int start = g_rowptr[w];
    int end   = g_rowptr[w + 1];
    float2 gr = ((const float2*)(g_gnn + (size_t)w * DD))[lane];
    float invr = g_invn[w];

    float rowsum = 0.f, fx = 0.f, fy = 0.f;
    int j = start;
    // unroll-by-2: two independent dot reductions in flight
    for (; j + 1 < end; j += 2) {
        int c0 = g_ecol[j];
        int c1 = g_ecol[j + 1];
        float2 gc0 = __ldg(((const float2*)(g_gnn + (size_t)c0 * DD)) + lane);
        float2 gc1 = __ldg(((const float2*)(g_gnn + (size_t)c1 * DD)) + lane);
        float2 v0  = __ldg(((const float2*)(cur_old + (size_t)c0 * DD)) + lane);
        float2 v1  = __ldg(((const float2*)(cur_old + (size_t)c1 * DD)) + lane);
        float ic0 = g_invn[c0];
        float ic1 = g_invn[c1];
        float d0 = gr.x * gc0.x + gr.y * gc0.y;
        float d1 = gr.x * gc1.x + gr.y * gc1.y;
        #pragma unroll
        for (int o = 16; o > 0; o >>= 1) {
            d0 += __shfl_xor_sync(0xFFFFFFFFu, d0, o);
            d1 += __shfl_xor_sync(0xFFFFFFFFu, d1, o);
        }
        float s0 = fmaf(d0, invr * ic0, 1.0f) * 0.5f;
        float s1 = fmaf(d1, invr * ic1, 1.0f) * 0.5f;
        rowsum += s0 + s1;
        fx = fmaf(s0, v0.x, fx);
        fy = fmaf(s0, v0.y, fy);
        fx = fmaf(s1, v1.x, fx);
        fy = fmaf(s1, v1.y, fy);
    }
    if (j < end) {
        int c = g_ecol[j];
        float2 gc = __ldg(((const float2*)(g_gnn + (size_t)c * DD)) + lane);
        float2 v  = __ldg(((const float2*)(cur_old + (size_t)c * DD)) + lane);
        float ic = g_invn[c];
        float d = gr.x * gc.x + gr.y * gc.y;
        #pragma unroll
        for (int o = 16; o > 0; o >>= 1) d += __shfl_xor_sync(0xFFFFFFFFu, d, o);
        float s = fmaf(d, invr * ic, 1.0f) * 0.5f;
        rowsum += s;
        fx = fmaf(s, v.x, fx);
        fy = fmaf(s, v.y, fy);
    }

    float dinv = rowsum > 0.f ? 1.0f / rowsum : 0.f;
    fx *= dinv;
    fy *= dinv;

    // fine slice -> out (stacked layout: [acc(N,D)][user_fine(L,U,D)][item_fine(L,I,D)])
    size_t fpos;
    if (w < UU)
        fpos = (size_t)NN * DD + (size_t)layer * UU * DD + (size_t)w * DD;
    else
        fpos = (size_t)NN * DD + (size_t)LL * UU * DD + (size_t)layer * II * DD
             + (size_t)(w - UU) * DD;
    ((float2*)(out + fpos))[lane] = make_float2(fx, fy);

    float cx = gr.x + fx, cy = gr.y + fy;           // cur_next = gnn + fine
    ((float2*)(cur_new + (size_t)w * DD))[lane] = make_float2(cx, cy);

    float2* o = (float2*)(out + (size_t)w * DD);    // acc += cur_next
    float2 ov = o[lane];
    o[lane] = make_float2(ov.x + cx, ov.y + cy);
}

// ---------------- launch ----------------
extern "C" void kernel_launch(void* const* d_in, const int* in_sizes, int n_in,
                              void* d_out, int out_size) {
    const float* user_emb = (const float*)d_in[0];
    const float* item_emb = (const float*)d_in[1];
    const int*   rows     = (const int*)d_in[2];
    const int*   cols     = (const int*)d_in[3];
    float* out = (float*)d_out;

    void *p_deg, *p_curA, *p_curB;
    cudaGetSymbolAddress(&p_deg, g_deg);
    cudaGetSymbolAddress(&p_curA, g_curA);
    cudaGetSymbolAddress(&p_curB, g_curB);

    cudaStream_t s = 0;
    const int TB = 256;
    const int grid_E    = (EE + TB - 1) / TB;
    const int grid_N    = (NN + TB - 1) / TB;
    const int grid_ND   = (NN * DD + TB - 1) / TB;
    const int grid_RowW = (NN * 32 + TB - 1) / TB;   // warp-per-row

    cudaMemsetAsync(p_deg, 0, NN * sizeof(int), s);
    hist_kernel<<<grid_E, TB, 0, s>>>(rows);
    scan1_kernel<<<NBLK, SCAN_B, 0, s>>>();
    scan2_kernel<<<1, 256, 0, s>>>();
    scan3_kernel<<<grid_N, TB, 0, s>>>();
    scatter_kernel<<<grid_E, TB, 0, s>>>(rows, cols);
    init_kernel<<<grid_ND, TB, 0, s>>>(user_emb, item_emb, out);

    float* bufA = (float*)p_curA;
    float* bufB = (float*)p_curB;
    for (int l = 0; l < LL; l++) {
        layer1_kernel<<<grid_RowW, TB, 0, s>>>(bufA);
        layer2_kernel<<<grid_RowW, TB, 0, s>>>(bufA, bufB, out, l);
        float* t = bufA; bufA = bufB; bufB = t;
    }
}

// round 5
// speedup vs baseline: 3.5176x; 1.1189x over previous
#include <cuda_runtime.h>
#include <cuda_fp16.h>
#include <math.h>

#define NN 150000
#define UU 100000
#define II 50000
#define DD 64
#define EE 2000000
#define LL 3
#define SCAN_B 1024
#define NBLK ((NN + SCAN_B - 1) / SCAN_B)   // 147

// -------- device scratch (no allocations allowed) --------
__device__ float   g_curA[NN * DD];
__device__ float   g_curB[NN * DD];
__device__ float   g_curS[NN * DD];        // dis ⊙ cur (pre-scaled for layer1)
__device__ float   g_gnn[NN * DD];
__device__ __half2 g_gnh[NN * (DD / 2)];   // normalized gnn, fp16
__device__ float   g_invn[NN];
__device__ float   g_dis[NN];
__device__ int     g_deg[NN];
__device__ int     g_rowptr[NN + 1];
__device__ int     g_cursor[NN];
__device__ int     g_ecol[EE];
__device__ int     g_bsum[NBLK + 1];
__device__ int     g_boff[NBLK + 1];

// ---------------- setup kernels ----------------

__global__ void hist_kernel(const int* __restrict__ rows) {
    int e = blockIdx.x * blockDim.x + threadIdx.x;
    if (e < EE) atomicAdd(&g_deg[rows[e]], 1);
}

// per-block inclusive scan of deg; also computes dis
__global__ void scan1_kernel() {
    __shared__ int s[SCAN_B];
    int i = blockIdx.x * SCAN_B + threadIdx.x;
    int v = (i < NN) ? g_deg[i] : 0;
    if (i < NN) g_dis[i] = v > 0 ? rsqrtf((float)v) : 0.f;
    s[threadIdx.x] = v;
    __syncthreads();
    #pragma unroll
    for (int off = 1; off < SCAN_B; off <<= 1) {
        int t = (threadIdx.x >= off) ? s[threadIdx.x - off] : 0;
        __syncthreads();
        s[threadIdx.x] += t;
        __syncthreads();
    }
    if (i < NN) g_rowptr[i + 1] = s[threadIdx.x];
    if (threadIdx.x == SCAN_B - 1) g_bsum[blockIdx.x] = s[SCAN_B - 1];
}

__global__ void scan2_kernel() {
    __shared__ int s[256];
    int t = threadIdx.x;
    int v = (t < NBLK) ? g_bsum[t] : 0;
    s[t] = v;
    __syncthreads();
    #pragma unroll
    for (int off = 1; off < 256; off <<= 1) {
        int x = (t >= off) ? s[t - off] : 0;
        __syncthreads();
        s[t] += x;
        __syncthreads();
    }
    if (t < NBLK) g_boff[t] = s[t] - v;
}

__global__ void scan3_kernel() {
    int i = blockIdx.x * blockDim.x + threadIdx.x;
    if (i == 0) g_rowptr[0] = 0;
    if (i < NN) {
        int fin = g_rowptr[i + 1] + g_boff[i / SCAN_B];
        g_rowptr[i + 1] = fin;
        g_cursor[i] = fin - g_deg[i];
    }
}

// scatter col indices into CSR order (no edge values needed anymore)
__global__ void scatter_kernel(const int* __restrict__ rows, const int* __restrict__ cols) {
    int e = blockIdx.x * blockDim.x + threadIdx.x;
    if (e >= EE) return;
    int r = rows[e];
    int pos = atomicAdd(&g_cursor[r], 1);
    g_ecol[pos] = cols[e];
}

// cur = emb0; curS = dis⊙emb0; out acc = emb0
__global__ void init_kernel(const float* __restrict__ user_emb,
                            const float* __restrict__ item_emb,
                            float* __restrict__ out) {
    int i = blockIdx.x * blockDim.x + threadIdx.x;
    if (i < NN * DD) {
        float v = (i < UU * DD) ? user_emb[i] : item_emb[i - UU * DD];
        g_curA[i] = v;
        g_curS[i] = v * g_dis[i >> 6];
        out[i] = v;
    }
}

// ---------------- per-layer kernels ----------------

// warp-per-row unweighted gather-sum: gnn[r] = dis[r] * sum_e curS[c_e]
// epilogue: invn + fp16 normalized row
__global__ void __launch_bounds__(256)
layer1_kernel(const float* __restrict__ curS) {
    int w = (blockIdx.x * blockDim.x + threadIdx.x) >> 5;
    int lane = threadIdx.x & 31;
    if (w >= NN) return;
    int start = g_rowptr[w];
    int end   = g_rowptr[w + 1];
    float ax0 = 0.f, ay0 = 0.f, ax1 = 0.f, ay1 = 0.f;
    int j = start;
    for (; j + 3 < end; j += 4) {
        int c0 = __ldg(g_ecol + j);
        int c1 = __ldg(g_ecol + j + 1);
        int c2 = __ldg(g_ecol + j + 2);
        int c3 = __ldg(g_ecol + j + 3);
        float2 v0 = __ldg(((const float2*)(curS + (size_t)c0 * DD)) + lane);
        float2 v1 = __ldg(((const float2*)(curS + (size_t)c1 * DD)) + lane);
        float2 v2 = __ldg(((const float2*)(curS + (size_t)c2 * DD)) + lane);
        float2 v3 = __ldg(((const float2*)(curS + (size_t)c3 * DD)) + lane);
        ax0 += v0.x + v2.x;  ay0 += v0.y + v2.y;
        ax1 += v1.x + v3.x;  ay1 += v1.y + v3.y;
    }
    for (; j < end; j++) {
        int c = __ldg(g_ecol + j);
        float2 v = __ldg(((const float2*)(curS + (size_t)c * DD)) + lane);
        ax0 += v.x;  ay0 += v.y;
    }
    float dr = g_dis[w];
    float ax = (ax0 + ax1) * dr;
    float ay = (ay0 + ay1) * dr;
    ((float2*)(g_gnn + (size_t)w * DD))[lane] = make_float2(ax, ay);
    float ss = ax * ax + ay * ay;
    #pragma unroll
    for (int o = 16; o > 0; o >>= 1) ss += __shfl_xor_sync(0xFFFFFFFFu, ss, o);
    float inv = 1.0f / fmaxf(sqrtf(ss), 1e-12f);
    if (lane == 0) g_invn[w] = inv;
    g_gnh[(size_t)w * 32 + lane] = __floats2half2_rn(ax * inv, ay * inv);
}

// warp-per-row fused single pass: scores (fp16 c-side) + rowsum + fine + finalize
__global__ void __launch_bounds__(256)
layer2_kernel(const float* __restrict__ cur_old,
              float* __restrict__ cur_new,
              float* __restrict__ out, int layer) {
    int w = (blockIdx.x * blockDim.x + threadIdx.x) >> 5;
    int lane = threadIdx.x & 31;
    if (w >= NN) return;
    int start = g_rowptr[w];
    int end   = g_rowptr[w + 1];
    float2 gfull = ((const float2*)(g_gnn + (size_t)w * DD))[lane];
    float invr = g_invn[w];
    float grx = gfull.x * invr, gry = gfull.y * invr;   // fp32 normalized r-side

    float rowsum = 0.f, fx = 0.f, fy = 0.f;
    int j = start;
    for (; j + 3 < end; j += 4) {
        int c0 = __ldg(g_ecol + j);
        int c1 = __ldg(g_ecol + j + 1);
        int c2 = __ldg(g_ecol + j + 2);
        int c3 = __ldg(g_ecol + j + 3);
        float2 q0 = __half22float2(__ldg(g_gnh + (size_t)c0 * 32 + lane));
        float2 q1 = __half22float2(__ldg(g_gnh + (size_t)c1 * 32 + lane));
        float2 q2 = __half22float2(__ldg(g_gnh + (size_t)c2 * 32 + lane));
        float2 q3 = __half22float2(__ldg(g_gnh + (size_t)c3 * 32 + lane));
        float2 v0 = __ldg(((const float2*)(cur_old + (size_t)c0 * DD)) + lane);
        float2 v1 = __ldg(((const float2*)(cur_old + (size_t)c1 * DD)) + lane);
        float2 v2 = __ldg(((const float2*)(cur_old + (size_t)c2 * DD)) + lane);
        float2 v3 = __ldg(((const float2*)(cur_old + (size_t)c3 * DD)) + lane);
        float d0 = grx * q0.x + gry * q0.y;
        float d1 = grx * q1.x + gry * q1.y;
        float d2 = grx * q2.x + gry * q2.y;
        float d3 = grx * q3.x + gry * q3.y;
        #pragma unroll
        for (int o = 16; o > 0; o >>= 1) {
            d0 += __shfl_xor_sync(0xFFFFFFFFu, d0, o);
            d1 += __shfl_xor_sync(0xFFFFFFFFu, d1, o);
            d2 += __shfl_xor_sync(0xFFFFFFFFu, d2, o);
            d3 += __shfl_xor_sync(0xFFFFFFFFu, d3, o);
        }
        float s0 = fmaf(d0, 0.5f, 0.5f);
        float s1 = fmaf(d1, 0.5f, 0.5f);
        float s2 = fmaf(d2, 0.5f, 0.5f);
        float s3 = fmaf(d3, 0.5f, 0.5f);
        rowsum += (s0 + s1) + (s2 + s3);
        fx = fmaf(s0, v0.x, fx);  fy = fmaf(s0, v0.y, fy);
        fx = fmaf(s1, v1.x, fx);  fy = fmaf(s1, v1.y, fy);
        fx = fmaf(s2, v2.x, fx);  fy = fmaf(s2, v2.y, fy);
        fx = fmaf(s3, v3.x, fx);  fy = fmaf(s3, v3.y, fy);
    }
    for (; j < end; j++) {
        int c = __ldg(g_ecol + j);
        float2 q = __half22float2(__ldg(g_gnh + (size_t)c * 32 + lane));
        float2 v = __ldg(((const float2*)(cur_old + (size_t)c * DD)) + lane);
        float d = grx * q.x + gry * q.y;
        #pragma unroll
        for (int o = 16; o > 0; o >>= 1) d += __shfl_xor_sync(0xFFFFFFFFu, d, o);
        float s = fmaf(d, 0.5f, 0.5f);
        rowsum += s;
        fx = fmaf(s, v.x, fx);  fy = fmaf(s, v.y, fy);
    }

    float dinv = rowsum > 0.f ? 1.0f / rowsum : 0.f;
    fx *= dinv;
    fy *= dinv;

    // fine slice -> out (stacked: [acc(N,D)][user_fine(L,U,D)][item_fine(L,I,D)])
    size_t fpos;
    if (w < UU)
        fpos = (size_t)NN * DD + (size_t)layer * UU * DD + (size_t)w * DD;
    else
        fpos = (size_t)NN * DD + (size_t)LL * UU * DD + (size_t)layer * II * DD
             + (size_t)(w - UU) * DD;
    ((float2*)(out + fpos))[lane] = make_float2(fx, fy);

    float cx = gfull.x + fx, cy = gfull.y + fy;       // cur_next = gnn + fine
    ((float2*)(cur_new + (size_t)w * DD))[lane] = make_float2(cx, cy);

    float dr = g_dis[w];                               // curS_next = dis ⊙ cur_next
    ((float2*)(g_curS + (size_t)w * DD))[lane] = make_float2(cx * dr, cy * dr);

    float2* o = (float2*)(out + (size_t)w * DD);       // acc += cur_next
    float2 ov = o[lane];
    o[lane] = make_float2(ov.x + cx, ov.y + cy);
}

// ---------------- launch ----------------
extern "C" void kernel_launch(void* const* d_in, const int* in_sizes, int n_in,
                              void* d_out, int out_size) {
    const float* user_emb = (const float*)d_in[0];
    const float* item_emb = (const float*)d_in[1];
    const int*   rows     = (const int*)d_in[2];
    const int*   cols     = (const int*)d_in[3];
    float* out = (float*)d_out;

    void *p_deg, *p_curA, *p_curB, *p_curS;
    cudaGetSymbolAddress(&p_deg, g_deg);
    cudaGetSymbolAddress(&p_curA, g_curA);
    cudaGetSymbolAddress(&p_curB, g_curB);
    cudaGetSymbolAddress(&p_curS, g_curS);

    cudaStream_t s = 0;
    const int TB = 256;
    const int grid_E    = (EE + TB - 1) / TB;
    const int grid_N    = (NN + TB - 1) / TB;
    const int grid_ND   = (NN * DD + TB - 1) / TB;
    const int grid_RowW = (NN * 32 + TB - 1) / TB;   // warp-per-row

    cudaMemsetAsync(p_deg, 0, NN * sizeof(int), s);
    hist_kernel<<<grid_E, TB, 0, s>>>(rows);
    scan1_kernel<<<NBLK, SCAN_B, 0, s>>>();
    scan2_kernel<<<1, 256, 0, s>>>();
    scan3_kernel<<<grid_N, TB, 0, s>>>();
    scatter_kernel<<<grid_E, TB, 0, s>>>(rows, cols);
    init_kernel<<<grid_ND, TB, 0, s>>>(user_emb, item_emb, out);

    float* bufA = (float*)p_curA;
    float* bufB = (float*)p_curB;
    for (int l = 0; l < LL; l++) {
        layer1_kernel<<<grid_RowW, TB, 0, s>>>((const float*)p_curS);
        layer2_kernel<<<grid_RowW, TB, 0, s>>>(bufA, bufB, out, l);
        float* t = bufA; bufA = bufB; bufB = t;
    }
}